// round 11
// baseline (speedup 1.0000x reference)
#include <cuda_runtime.h>
#include <cstdint>

// Submanifold sparse conv — compacted per-offset gather-GEMM, quad-pipelined.
//  fused_kernel  : blocks [0,CEN_BLOCKS) -> center GEMM (out = bias + F@W13);
//                  rest -> element-parallel compaction (independent inputs).
//  taps_kernel   : out[site] += F[nb] @ W[k]; W[k] in registers; 4 taps/iter,
//                  2-deep entry pipeline, coalesced per-lane atomicAdd epilogue.
//                  Counters self-reset: last block per k zeroes g_count/g_done,
//                  so no separate zero launch is needed (globals start zeroed).

#define C 32
#define KTAPS 27
#define KCENTER 13
#define NCAP 131072

__device__ int  g_count[KTAPS];          // zero at module load
__device__ int  g_done[KTAPS];           // zero at module load
__device__ int2 g_list[KTAPS * NCAP];

// ---------------------------------------------------------------- fused center + compact
#define FB_THREADS 256
#define CEN_BLOCKS 592
#define CB_EPT 16
#define CB_ELEMS (FB_THREADS * CB_EPT)   // 4096 elements per compact block

__global__ void __launch_bounds__(FB_THREADS)
fused_kernel(const float* __restrict__ features,
             const float* __restrict__ weight,
             const float* __restrict__ bias,
             const int*   __restrict__ nbr_idx,
             const int*   __restrict__ nbr_mask,
             float* __restrict__ out,
             int n_sites, int n_elems)
{
    __shared__ union {
        struct { int scount[KTAPS]; int sbase[KTAPS]; } cp;
        float rows[FB_THREADS / 32][C];
    } sm;

    const int tid  = threadIdx.x;
    const int lane = tid & 31;
    const int wib  = tid >> 5;

    if (blockIdx.x < CEN_BLOCKS) {
        // ---------------- center GEMM ----------------
        float w[C];
        const float* w13 = weight + KCENTER * C * C;
        #pragma unroll
        for (int ci = 0; ci < C; ++ci)
            w[ci] = w13[ci * C + lane];

        const float my_bias = bias[lane];
        float* row = sm.rows[wib];

        const int gwarp  = blockIdx.x * (FB_THREADS / 32) + wib;
        const int nwarps = CEN_BLOCKS * (FB_THREADS / 32);

        float fvA = 0.f;
        if (gwarp < n_sites) fvA = features[gwarp * C + lane];

        for (int site = gwarp; site < n_sites; site += nwarps) {
            const int nsite = site + nwarps;
            float fvB = 0.f;
            if (nsite < n_sites) fvB = features[nsite * C + lane];

            row[lane] = fvA;
            __syncwarp();

            float a0 = my_bias, a1 = 0.f, a2 = 0.f, a3 = 0.f;
            #pragma unroll
            for (int g = 0; g < 8; ++g) {
                const float4 f = *reinterpret_cast<const float4*>(row + (g << 2));
                a0 += f.x * w[(g << 2) + 0];
                a1 += f.y * w[(g << 2) + 1];
                a2 += f.z * w[(g << 2) + 2];
                a3 += f.w * w[(g << 2) + 3];
            }
            __syncwarp();

            out[site * C + lane] = (a0 + a1) + (a2 + a3);
            fvA = fvB;
        }
    } else {
        // ---------------- compaction (coalesced) ----------------
        if (tid < KTAPS) sm.cp.scount[tid] = 0;
        __syncthreads();

        const int base = (blockIdx.x - CEN_BLOCKS) * CB_ELEMS;
        bool act[CB_EPT];

        #pragma unroll
        for (int s = 0; s < CB_EPT; ++s) {
            const int e = base + s * FB_THREADS + tid;
            bool a = false;
            if (e < n_elems) {
                const int k = e % KTAPS;
                a = (k != KCENTER) && (nbr_mask[e] != 0);
                if (a) atomicAdd(&sm.cp.scount[k], 1);
            }
            act[s] = a;
        }
        __syncthreads();

        if (tid < KTAPS) {
            const int c = sm.cp.scount[tid];
            sm.cp.sbase[tid]  = c ? atomicAdd(&g_count[tid], c) : 0;
            sm.cp.scount[tid] = 0;
        }
        __syncthreads();

        #pragma unroll
        for (int s = 0; s < CB_EPT; ++s) {
            if (act[s]) {
                const int e    = base + s * FB_THREADS + tid;
                const int site = e / KTAPS;
                const int k    = e - site * KTAPS;
                const int pos  = sm.cp.sbase[k] + atomicAdd(&sm.cp.scount[k], 1);
                g_list[k * NCAP + pos] = make_int2(site, nbr_idx[e]);
            }
        }
    }
}

// ---------------------------------------------------------------- taps
#define PB_WARPS 8
#define PB_THREADS 256
#define PB_BLOCKS_X 17      // 26*17 = 442 blocks ~= one wave at 3 blocks/SM

__global__ void __launch_bounds__(PB_THREADS, 3)
taps_kernel(const float* __restrict__ features,
            const float* __restrict__ weight,
            float* __restrict__ out)
{
    // 2 buffers x 4 rows per warp
    __shared__ float rows[PB_WARPS][8][C];

    int k = blockIdx.y;
    if (k >= KCENTER) ++k;

    const int tid  = threadIdx.x;
    const int lane = tid & 31;
    const int wib  = tid >> 5;

    float w[C];
    const float* wkp = weight + k * C * C;
    #pragma unroll
    for (int ci = 0; ci < C; ++ci)
        w[ci] = wkp[ci * C + lane];

    const int cnt    = g_count[k];        // every block reads BEFORE its g_done inc
    const int nquads = cnt >> 2;
    const int warps_per_k = gridDim.x * PB_WARPS;
    const int wid_in_k = blockIdx.x * PB_WARPS + wib;
    const int chunk = (nquads + warps_per_k - 1) / warps_per_k;
    int q = wid_in_k * chunk;
    const int qend = min(q + chunk, nquads);

    const int4* list4 = reinterpret_cast<const int4*>(g_list + k * NCAP);
    float (*myrows)[C] = rows[wib];

    if (q < qend) {
        int4 a0 = list4[2 * q], a1 = list4[2 * q + 1];
        int4 b0 = a0, b1 = a1;
        if (q + 1 < qend) { b0 = list4[2 * q + 2]; b1 = list4[2 * q + 3]; }
        float fA0 = features[a0.y * C + lane];
        float fA1 = features[a0.w * C + lane];
        float fA2 = features[a1.y * C + lane];
        float fA3 = features[a1.w * C + lane];

        for (;;) {
            const bool hasB = (q + 1 < qend);

            int4 c0 = a0, c1 = a1;
            if (q + 2 < qend) { c0 = list4[2 * q + 4]; c1 = list4[2 * q + 5]; }
            float fB0 = 0.f, fB1 = 0.f, fB2 = 0.f, fB3 = 0.f;
            if (hasB) {
                fB0 = features[b0.y * C + lane];
                fB1 = features[b0.w * C + lane];
                fB2 = features[b1.y * C + lane];
                fB3 = features[b1.w * C + lane];
            }

            const int buf = (q & 1) << 2;
            myrows[buf + 0][lane] = fA0;
            myrows[buf + 1][lane] = fA1;
            myrows[buf + 2][lane] = fA2;
            myrows[buf + 3][lane] = fA3;
            __syncwarp();

            float t0 = 0.f, t1 = 0.f, t2 = 0.f, t3 = 0.f;
            #pragma unroll
            for (int g = 0; g < 8; ++g) {
                const float4 f0 = *reinterpret_cast<const float4*>(myrows[buf + 0] + (g << 2));
                const float4 f1 = *reinterpret_cast<const float4*>(myrows[buf + 1] + (g << 2));
                const float4 f2 = *reinterpret_cast<const float4*>(myrows[buf + 2] + (g << 2));
                const float4 f3 = *reinterpret_cast<const float4*>(myrows[buf + 3] + (g << 2));
                const float w0 = w[(g << 2) + 0];
                const float w1 = w[(g << 2) + 1];
                const float w2 = w[(g << 2) + 2];
                const float w3 = w[(g << 2) + 3];
                t0 += f0.x * w0; t0 += f0.y * w1; t0 += f0.z * w2; t0 += f0.w * w3;
                t1 += f1.x * w0; t1 += f1.y * w1; t1 += f1.z * w2; t1 += f1.w * w3;
                t2 += f2.x * w0; t2 += f2.y * w1; t2 += f2.z * w2; t2 += f2.w * w3;
                t3 += f3.x * w0; t3 += f3.y * w1; t3 += f3.z * w2; t3 += f3.w * w3;
            }

            atomicAdd(&out[a0.x * C + lane], t0);
            atomicAdd(&out[a0.z * C + lane], t1);
            atomicAdd(&out[a1.x * C + lane], t2);
            atomicAdd(&out[a1.z * C + lane], t3);

            if (!hasB) break;
            ++q;
            a0 = b0; a1 = b1; b0 = c0; b1 = c1;
            fA0 = fB0; fA1 = fB1; fA2 = fB2; fA3 = fB3;
        }
    }

    // ---- tail (cnt & 3 taps), handled by warp 0 of this k ----
    if (wid_in_k == 0) {
        const int2* list = g_list + k * NCAP;
        for (int t = nquads << 2; t < cnt; ++t) {
            const int2 ent = list[t];
            const float fv = features[ent.y * C + lane];
            myrows[0][lane] = fv;
            __syncwarp();
            float acc = 0.f;
            #pragma unroll
            for (int g = 0; g < 8; ++g) {
                const float4 f = *reinterpret_cast<const float4*>(myrows[0] + (g << 2));
                acc += f.x * w[(g << 2) + 0];
                acc += f.y * w[(g << 2) + 1];
                acc += f.z * w[(g << 2) + 2];
                acc += f.w * w[(g << 2) + 3];
            }
            __syncwarp();
            atomicAdd(&out[ent.x * C + lane], acc);
        }
    }

    // ---- self-reset: last block for this k zeroes the counters ----
    __syncthreads();                       // all warps past their g_count read/work
    if (tid == 0) {
        const int d = atomicAdd(&g_done[k], 1);
        if (d == gridDim.x - 1) {          // 17th (last) block for this k
            g_count[k] = 0;
            g_done[k]  = 0;
        }
    }
}

// ---------------------------------------------------------------- launch
extern "C" void kernel_launch(void* const* d_in, const int* in_sizes, int n_in,
                              void* d_out, int out_size)
{
    const float* features = (const float*)d_in[0];
    const float* weight   = (const float*)d_in[1];
    const float* bias     = (const float*)d_in[2];
    const int*   nbr_idx  = (const int*)d_in[3];
    const int*   nbr_mask = (const int*)d_in[4];
    float*       out      = (float*)d_out;

    const int n_sites = in_sizes[0] / C;
    const int n_elems = n_sites * KTAPS;

    const int cblocks = (n_elems + CB_ELEMS - 1) / CB_ELEMS;
    fused_kernel<<<CEN_BLOCKS + cblocks, FB_THREADS>>>(
        features, weight, bias, nbr_idx, nbr_mask, out, n_sites, n_elems);

    dim3 tgrid(PB_BLOCKS_X, KTAPS - 1);
    taps_kernel<<<tgrid, PB_THREADS>>>(features, weight, out);
}

// round 12
// speedup vs baseline: 1.0680x; 1.0680x over previous
#include <cuda_runtime.h>
#include <cstdint>

// Submanifold sparse conv — compacted per-offset gather-GEMM, quad-pipelined,
// packed f32x2 FFMA inner loops.
//  zero_kernel   : reset per-k counters
//  fused_kernel  : blocks [0,CEN_BLOCKS) -> center GEMM (out = bias + F@W13);
//                  rest -> element-parallel compaction (independent inputs).
//  taps_kernel   : out[site] += F[nb] @ W[k]; W[k] packed in b64 registers;
//                  4 taps/iter, 2-deep entry pipeline, coalesced atomicAdd.

#define C 32
#define KTAPS 27
#define KCENTER 13
#define NCAP 131072

__device__ int  g_count[KTAPS];
__device__ int2 g_list[KTAPS * NCAP];

typedef unsigned long long u64;

__device__ __forceinline__ u64 fma_f32x2(u64 a, u64 b, u64 c)
{
    u64 d;
    asm("fma.rn.f32x2 %0, %1, %2, %3;" : "=l"(d) : "l"(a), "l"(b), "l"(c));
    return d;
}
__device__ __forceinline__ u64 pack_f32x2(float lo, float hi)
{
    u64 d;
    asm("mov.b64 %0, {%1, %2};" : "=l"(d) : "f"(lo), "f"(hi));
    return d;
}
__device__ __forceinline__ float sum_f32x2(u64 v)
{
    float lo, hi;
    asm("mov.b64 {%0, %1}, %2;" : "=f"(lo), "=f"(hi) : "l"(v));
    return lo + hi;
}

// ---------------------------------------------------------------- zero
__global__ void zero_kernel()
{
    if (threadIdx.x < KTAPS) g_count[threadIdx.x] = 0;
}

// ---------------------------------------------------------------- fused center + compact
#define FB_THREADS 256
#define CEN_BLOCKS 592
#define CB_EPT 8
#define CB_ELEMS (FB_THREADS * CB_EPT)

__global__ void __launch_bounds__(FB_THREADS)
fused_kernel(const float* __restrict__ features,
             const float* __restrict__ weight,
             const float* __restrict__ bias,
             const int*   __restrict__ nbr_idx,
             const int*   __restrict__ nbr_mask,
             float* __restrict__ out,
             int n_sites, int n_elems)
{
    __shared__ union {
        struct { int scount[KTAPS]; int sbase[KTAPS]; } cp;
        float rows[FB_THREADS / 32][C];
    } sm;

    const int tid  = threadIdx.x;
    const int lane = tid & 31;
    const int wib  = tid >> 5;

    if (blockIdx.x < CEN_BLOCKS) {
        // ---------------- center GEMM ----------------
        u64 w2[C / 2];
        const float* w13 = weight + KCENTER * C * C;
        #pragma unroll
        for (int g = 0; g < C / 2; ++g)
            w2[g] = pack_f32x2(w13[(2 * g) * C + lane], w13[(2 * g + 1) * C + lane]);

        const float my_bias = bias[lane];
        float* row = sm.rows[wib];

        const int gwarp  = blockIdx.x * (FB_THREADS / 32) + wib;
        const int nwarps = CEN_BLOCKS * (FB_THREADS / 32);

        float fvA = 0.f;
        if (gwarp < n_sites) fvA = features[gwarp * C + lane];

        for (int site = gwarp; site < n_sites; site += nwarps) {
            const int nsite = site + nwarps;
            float fvB = 0.f;
            if (nsite < n_sites) fvB = features[nsite * C + lane];

            row[lane] = fvA;
            __syncwarp();

            u64 ta = 0ull, tb = 0ull;
            #pragma unroll
            for (int g = 0; g < 8; ++g) {
                const ulonglong2 fp = *reinterpret_cast<const ulonglong2*>(row + (g << 2));
                ta = fma_f32x2(fp.x, w2[2 * g + 0], ta);
                tb = fma_f32x2(fp.y, w2[2 * g + 1], tb);
            }
            __syncwarp();

            out[site * C + lane] = my_bias + sum_f32x2(ta) + sum_f32x2(tb);
            fvA = fvB;
        }
    } else {
        // ---------------- compaction (coalesced) ----------------
        if (tid < KTAPS) sm.cp.scount[tid] = 0;
        __syncthreads();

        const int base = (blockIdx.x - CEN_BLOCKS) * CB_ELEMS;
        bool act[CB_EPT];

        #pragma unroll
        for (int s = 0; s < CB_EPT; ++s) {
            const int e = base + s * FB_THREADS + tid;
            bool a = false;
            if (e < n_elems) {
                const int k = e % KTAPS;
                a = (k != KCENTER) && (nbr_mask[e] != 0);
                if (a) atomicAdd(&sm.cp.scount[k], 1);
            }
            act[s] = a;
        }
        __syncthreads();

        if (tid < KTAPS) {
            const int c = sm.cp.scount[tid];
            sm.cp.sbase[tid]  = c ? atomicAdd(&g_count[tid], c) : 0;
            sm.cp.scount[tid] = 0;
        }
        __syncthreads();

        #pragma unroll
        for (int s = 0; s < CB_EPT; ++s) {
            if (act[s]) {
                const int e    = base + s * FB_THREADS + tid;
                const int site = e / KTAPS;
                const int k    = e - site * KTAPS;
                const int pos  = sm.cp.sbase[k] + atomicAdd(&sm.cp.scount[k], 1);
                g_list[k * NCAP + pos] = make_int2(site, nbr_idx[e]);
            }
        }
    }
}

// ---------------------------------------------------------------- taps
#define PB_WARPS 8
#define PB_THREADS 256
#define PB_BLOCKS_X 17      // 26*17 = 442 blocks ~= one wave at 3 blocks/SM

__global__ void __launch_bounds__(PB_THREADS, 3)
taps_kernel(const float* __restrict__ features,
            const float* __restrict__ weight,
            float* __restrict__ out)
{
    __shared__ float rows[PB_WARPS][8][C];

    int k = blockIdx.y;
    if (k >= KCENTER) ++k;

    const int tid  = threadIdx.x;
    const int lane = tid & 31;
    const int wib  = tid >> 5;

    // W[k] packed: w2[g] = (w[2g][lane], w[2g+1][lane])
    u64 w2[C / 2];
    const float* wkp = weight + k * C * C;
    #pragma unroll
    for (int g = 0; g < C / 2; ++g)
        w2[g] = pack_f32x2(wkp[(2 * g) * C + lane], wkp[(2 * g + 1) * C + lane]);

    const int cnt    = g_count[k];
    const int nquads = cnt >> 2;
    const int warps_per_k = gridDim.x * PB_WARPS;
    const int wid_in_k = blockIdx.x * PB_WARPS + wib;
    const int chunk = (nquads + warps_per_k - 1) / warps_per_k;
    int q = wid_in_k * chunk;
    const int qend = min(q + chunk, nquads);

    const int4* list4 = reinterpret_cast<const int4*>(g_list + k * NCAP);
    float (*myrows)[C] = rows[wib];

    if (q < qend) {
        int4 a0 = list4[2 * q], a1 = list4[2 * q + 1];
        int4 b0 = a0, b1 = a1;
        if (q + 1 < qend) { b0 = list4[2 * q + 2]; b1 = list4[2 * q + 3]; }
        float fA0 = features[a0.y * C + lane];
        float fA1 = features[a0.w * C + lane];
        float fA2 = features[a1.y * C + lane];
        float fA3 = features[a1.w * C + lane];

        for (;;) {
            const bool hasB = (q + 1 < qend);

            int4 c0 = a0, c1 = a1;
            if (q + 2 < qend) { c0 = list4[2 * q + 4]; c1 = list4[2 * q + 5]; }
            float fB0 = 0.f, fB1 = 0.f, fB2 = 0.f, fB3 = 0.f;
            if (hasB) {
                fB0 = features[b0.y * C + lane];
                fB1 = features[b0.w * C + lane];
                fB2 = features[b1.y * C + lane];
                fB3 = features[b1.w * C + lane];
            }

            const int buf = (q & 1) << 2;
            myrows[buf + 0][lane] = fA0;
            myrows[buf + 1][lane] = fA1;
            myrows[buf + 2][lane] = fA2;
            myrows[buf + 3][lane] = fA3;
            __syncwarp();

            u64 t0 = 0ull, t1 = 0ull, t2 = 0ull, t3 = 0ull;
            #pragma unroll
            for (int g = 0; g < 8; ++g) {
                const ulonglong2 f0 = *reinterpret_cast<const ulonglong2*>(myrows[buf + 0] + (g << 2));
                const ulonglong2 f1 = *reinterpret_cast<const ulonglong2*>(myrows[buf + 1] + (g << 2));
                const ulonglong2 f2 = *reinterpret_cast<const ulonglong2*>(myrows[buf + 2] + (g << 2));
                const ulonglong2 f3 = *reinterpret_cast<const ulonglong2*>(myrows[buf + 3] + (g << 2));
                const u64 wa = w2[2 * g + 0];
                const u64 wb = w2[2 * g + 1];
                t0 = fma_f32x2(f0.x, wa, t0); t0 = fma_f32x2(f0.y, wb, t0);
                t1 = fma_f32x2(f1.x, wa, t1); t1 = fma_f32x2(f1.y, wb, t1);
                t2 = fma_f32x2(f2.x, wa, t2); t2 = fma_f32x2(f2.y, wb, t2);
                t3 = fma_f32x2(f3.x, wa, t3); t3 = fma_f32x2(f3.y, wb, t3);
            }

            atomicAdd(&out[a0.x * C + lane], sum_f32x2(t0));
            atomicAdd(&out[a0.z * C + lane], sum_f32x2(t1));
            atomicAdd(&out[a1.x * C + lane], sum_f32x2(t2));
            atomicAdd(&out[a1.z * C + lane], sum_f32x2(t3));

            if (!hasB) break;
            ++q;
            a0 = b0; a1 = b1; b0 = c0; b1 = c1;
            fA0 = fB0; fA1 = fB1; fA2 = fB2; fA3 = fB3;
        }
    }

    // ---- tail (cnt & 3 taps), handled by warp 0 of this k ----
    if (wid_in_k == 0) {
        const int2* list = g_list + k * NCAP;
        for (int t = nquads << 2; t < cnt; ++t) {
            const int2 ent = list[t];
            const float fv = features[ent.y * C + lane];
            myrows[0][lane] = fv;
            __syncwarp();
            u64 acc = 0ull;
            #pragma unroll
            for (int g = 0; g < 8; ++g) {
                const ulonglong2 f = *reinterpret_cast<const ulonglong2*>(myrows[0] + (g << 2));
                acc = fma_f32x2(f.x, w2[2 * g + 0], acc);
                acc = fma_f32x2(f.y, w2[2 * g + 1], acc);
            }
            __syncwarp();
            atomicAdd(&out[ent.x * C + lane], sum_f32x2(acc));
        }
    }
}

// ---------------------------------------------------------------- launch
extern "C" void kernel_launch(void* const* d_in, const int* in_sizes, int n_in,
                              void* d_out, int out_size)
{
    const float* features = (const float*)d_in[0];
    const float* weight   = (const float*)d_in[1];
    const float* bias     = (const float*)d_in[2];
    const int*   nbr_idx  = (const int*)d_in[3];
    const int*   nbr_mask = (const int*)d_in[4];
    float*       out      = (float*)d_out;

    const int n_sites = in_sizes[0] / C;
    const int n_elems = n_sites * KTAPS;

    zero_kernel<<<1, 32>>>();

    const int cblocks = (n_elems + CB_ELEMS - 1) / CB_ELEMS;
    fused_kernel<<<CEN_BLOCKS + cblocks, FB_THREADS>>>(
        features, weight, bias, nbr_idx, nbr_mask, out, n_sites, n_elems);

    dim3 tgrid(PB_BLOCKS_X, KTAPS - 1);
    taps_kernel<<<tgrid, PB_THREADS>>>(features, weight, out);
}